// round 7
// baseline (speedup 1.0000x reference)
#include <cuda_runtime.h>
#include <cuda_bf16.h>
#include <cstdint>

#define DIM   512
#define N_CB  8192
#define M_Z   32768
#define QN    16777216   // M_Z * DIM
#define CAP   32
#define MARGIN 0.2f

// coarse kernel geometry
#define CTA_M        224
#define GRID_COARSE  147           // 147*224 = 32928 >= 32768
#define A_STAGE_B    (CTA_M * 128) // 28672
#define B_STAGE_B    (128 * 128)   // 16384
#define STAGE_B      (A_STAGE_B + B_STAGE_B)
#define SCNT_OFF     (STAGE_B * 4)            // 180224
#define COARSE_SMEM  (SCNT_OFF + CTA_M * 4)   // 181120
#define NSTAGES_K    512           // 64 tiles * 8 k-stages

// ---- scratch (device globals; no allocation) ----
__device__ float g_qcb[(size_t)N_CB * DIM];           // quant_codebook fp32 (16MB)
__device__ float g_u  [(size_t)N_CB * DIM];           // U = diag(1/||c||) (qcb @ W) fp32 (16MB)
__device__ __nv_bfloat16 g_ub[(size_t)N_CB * DIM];    // U bf16 (8MB)
__device__ __nv_bfloat16 g_zb[(size_t)M_Z * DIM];     // z bf16 (32MB)
__device__ float g_rs  [N_CB];                        // 1/||c||
__device__ float g_beta[N_CB];                        // (b . c)/||c||
__device__ unsigned g_cand[(size_t)M_Z * CAP];
__device__ int   g_ccnt[M_Z];
__device__ int   g_idx[M_Z];
__device__ float g_partial[M_Z];

// ============================================================
// base-ISA PTX helpers
// ============================================================
__device__ __forceinline__ uint32_t smem_u32(const void* p) {
    uint32_t a;
    asm("{ .reg .u64 t; cvta.to.shared.u64 t, %1; cvt.u32.u64 %0, t; }" : "=r"(a) : "l"(p));
    return a;
}
__device__ __forceinline__ void cp16(uint32_t dst, const void* src) {
    asm volatile("cp.async.cg.shared.global [%0], [%1], 16;" :: "r"(dst), "l"(src) : "memory");
}
#define CP_COMMIT() asm volatile("cp.async.commit_group;" ::: "memory")
#define CP_WAIT(N)  asm volatile("cp.async.wait_group %0;" :: "n"(N) : "memory")

__device__ __forceinline__ void ldmatrix_x4(uint32_t* r, uint32_t addr) {
    asm volatile("ldmatrix.sync.aligned.m8n8.x4.shared.b16 {%0,%1,%2,%3}, [%4];"
        : "=r"(r[0]), "=r"(r[1]), "=r"(r[2]), "=r"(r[3]) : "r"(addr));
}
__device__ __forceinline__ void mma_bf16(float* d, const uint32_t* a, uint32_t b0, uint32_t b1) {
    asm volatile("mma.sync.aligned.m16n8k16.row.col.f32.bf16.bf16.f32 "
        "{%0,%1,%2,%3}, {%4,%5,%6,%7}, {%8,%9}, {%0,%1,%2,%3};"
        : "+f"(d[0]), "+f"(d[1]), "+f"(d[2]), "+f"(d[3])
        : "r"(a[0]), "r"(a[1]), "r"(a[2]), "r"(a[3]), "r"(b0), "r"(b1));
}

// ============================================================
// K1: qcb = emb @ emb_w^T + emb_b   (NT, fp32)  128x128 tiles
// ============================================================
__global__ __launch_bounds__(256, 2)
void gemm_bias_nt(const float* __restrict__ A, const float* __restrict__ W,
                  const float* __restrict__ bias, int K)
{
    __shared__ float As[16][128];
    __shared__ float Ws[16][128];
    const int tid = threadIdx.x;
    const int tx  = tid & 15;
    const int ty  = tid >> 4;
    const int row0 = blockIdx.y * 128;
    const int col0 = blockIdx.x * 128;

    float acc[8][8];
    #pragma unroll
    for (int i = 0; i < 8; i++)
        #pragma unroll
        for (int j = 0; j < 8; j++) acc[i][j] = 0.0f;

    for (int k0 = 0; k0 < K; k0 += 16) {
        #pragma unroll
        for (int v = tid; v < 512; v += 256) {
            int r  = v >> 2;
            int kc = (v & 3) << 2;
            float4 a = *(const float4*)(A + (size_t)(row0 + r) * K + k0 + kc);
            As[kc + 0][r] = a.x; As[kc + 1][r] = a.y;
            As[kc + 2][r] = a.z; As[kc + 3][r] = a.w;
            float4 w = *(const float4*)(W + (size_t)(col0 + r) * K + k0 + kc);
            Ws[kc + 0][r] = w.x; Ws[kc + 1][r] = w.y;
            Ws[kc + 2][r] = w.z; Ws[kc + 3][r] = w.w;
        }
        __syncthreads();
        #pragma unroll
        for (int kk = 0; kk < 16; kk++) {
            float a[8], b[8];
            *(float4*)(a)     = *(const float4*)&As[kk][ty * 8];
            *(float4*)(a + 4) = *(const float4*)&As[kk][ty * 8 + 4];
            *(float4*)(b)     = *(const float4*)&Ws[kk][tx * 8];
            *(float4*)(b + 4) = *(const float4*)&Ws[kk][tx * 8 + 4];
            #pragma unroll
            for (int i = 0; i < 8; i++)
                #pragma unroll
                for (int j = 0; j < 8; j++)
                    acc[i][j] = fmaf(a[i], b[j], acc[i][j]);
        }
        __syncthreads();
    }

    float bs[8];
    #pragma unroll
    for (int j = 0; j < 8; j++) bs[j] = bias[col0 + tx * 8 + j];

    #pragma unroll
    for (int i = 0; i < 8; i++) {
        size_t row = (size_t)(row0 + ty * 8 + i);
        float* cp = g_qcb + row * DIM + col0 + tx * 8;
        *(float4*)(cp)     = make_float4(acc[i][0]+bs[0], acc[i][1]+bs[1], acc[i][2]+bs[2], acc[i][3]+bs[3]);
        *(float4*)(cp + 4) = make_float4(acc[i][4]+bs[4], acc[i][5]+bs[5], acc[i][6]+bs[6], acc[i][7]+bs[7]);
    }
}

// ============================================================
// K2: per-row 1/||c|| and beta = (z_proj_b . c)/||c||    (warp/row)
// ============================================================
__global__ void rownorm_beta(const float* __restrict__ zpb)
{
    int row  = blockIdx.x * 8 + (threadIdx.x >> 5);
    int lane = threadIdx.x & 31;
    const float* x = g_qcb + (size_t)row * DIM;
    float s2 = 0.0f, sb = 0.0f;
    #pragma unroll
    for (int it = 0; it < 4; it++) {
        float4 v = *(const float4*)(x + lane * 4 + it * 128);
        float4 b = *(const float4*)(zpb + lane * 4 + it * 128);
        s2 += v.x*v.x + v.y*v.y + v.z*v.z + v.w*v.w;
        sb += v.x*b.x + v.y*b.y + v.z*b.z + v.w*b.w;
    }
    #pragma unroll
    for (int off = 16; off > 0; off >>= 1) {
        s2 += __shfl_xor_sync(0xFFFFFFFFu, s2, off);
        sb += __shfl_xor_sync(0xFFFFFFFFu, sb, off);
    }
    float rs = 1.0f / fmaxf(sqrtf(s2), 1e-12f);
    if (lane == 0) { g_rs[row] = rs; g_beta[row] = sb * rs; }
}

// ============================================================
// K3: U = (g_qcb @ W) * rs[row]   (NN, fp32)  -> g_u fp32 + g_ub bf16
// ============================================================
__global__ __launch_bounds__(256, 2)
void gemm_nn_scaled(const float* __restrict__ W)
{
    __shared__ float As[16][128];
    __shared__ float Ws[16][128];
    const int tid = threadIdx.x;
    const int tx  = tid & 15;
    const int ty  = tid >> 4;
    const int row0 = blockIdx.y * 128;
    const int col0 = blockIdx.x * 128;
    const float* __restrict__ A = g_qcb;

    float acc[8][8];
    #pragma unroll
    for (int i = 0; i < 8; i++)
        #pragma unroll
        for (int j = 0; j < 8; j++) acc[i][j] = 0.0f;

    for (int k0 = 0; k0 < DIM; k0 += 16) {
        #pragma unroll
        for (int v = tid; v < 512; v += 256) {
            int r  = v >> 2;
            int kc = (v & 3) << 2;
            float4 a = *(const float4*)(A + (size_t)(row0 + r) * DIM + k0 + kc);
            As[kc + 0][r] = a.x; As[kc + 1][r] = a.y;
            As[kc + 2][r] = a.z; As[kc + 3][r] = a.w;
        }
        #pragma unroll
        for (int v = tid; v < 512; v += 256) {
            int kk = v >> 5;
            int nc = (v & 31) * 4;
            float4 w = *(const float4*)(W + (size_t)(k0 + kk) * DIM + col0 + nc);
            *(float4*)&Ws[kk][nc] = w;
        }
        __syncthreads();
        #pragma unroll
        for (int kk = 0; kk < 16; kk++) {
            float a[8], b[8];
            *(float4*)(a)     = *(const float4*)&As[kk][ty * 8];
            *(float4*)(a + 4) = *(const float4*)&As[kk][ty * 8 + 4];
            *(float4*)(b)     = *(const float4*)&Ws[kk][tx * 8];
            *(float4*)(b + 4) = *(const float4*)&Ws[kk][tx * 8 + 4];
            #pragma unroll
            for (int i = 0; i < 8; i++)
                #pragma unroll
                for (int j = 0; j < 8; j++)
                    acc[i][j] = fmaf(a[i], b[j], acc[i][j]);
        }
        __syncthreads();
    }

    #pragma unroll
    for (int i = 0; i < 8; i++) {
        size_t row = (size_t)(row0 + ty * 8 + i);
        float s = g_rs[row];
        float o[8];
        #pragma unroll
        for (int j = 0; j < 8; j++) o[j] = acc[i][j] * s;
        float* up = g_u + row * DIM + col0 + tx * 8;
        *(float4*)(up)     = make_float4(o[0], o[1], o[2], o[3]);
        *(float4*)(up + 4) = make_float4(o[4], o[5], o[6], o[7]);
        __nv_bfloat162* bp = (__nv_bfloat162*)(g_ub + row * DIM + col0 + tx * 8);
        bp[0] = __floats2bfloat162_rn(o[0], o[1]);
        bp[1] = __floats2bfloat162_rn(o[2], o[3]);
        bp[2] = __floats2bfloat162_rn(o[4], o[5]);
        bp[3] = __floats2bfloat162_rn(o[6], o[7]);
    }
}

// ============================================================
// K4: z -> bf16
// ============================================================
__global__ void convert_z(const float* __restrict__ z)
{
    long long n4 = QN / 4;
    long long stride = (long long)gridDim.x * blockDim.x;
    for (long long i = (long long)blockIdx.x * blockDim.x + threadIdx.x; i < n4; i += stride) {
        float4 v = ((const float4*)z)[i];
        __nv_bfloat162 p0 = __floats2bfloat162_rn(v.x, v.y);
        __nv_bfloat162 p1 = __floats2bfloat162_rn(v.z, v.w);
        uint2 o;
        o.x = *(uint32_t*)&p0;
        o.y = *(uint32_t*)&p1;
        ((uint2*)g_zb)[i] = o;
    }
}

// ============================================================
// K5: coarse bf16 HMMA pass, single wave.
// 147 CTAs x 224 rows; both A and B streamed, 4-stage cp.async
// pipeline (45KB/stage), one __syncthreads per k-stage.
// 8 warps as 2(m) x 4(n): warp tile m112 x n32.
// ============================================================
__global__ __launch_bounds__(256)
void coarse_kernel()
{
    extern __shared__ char sm[];
    const uint32_t smS = smem_u32(sm);
    int* scnt = (int*)(sm + SCNT_OFF);

    const int tid  = threadIdx.x;
    const int lane = tid & 31;
    const int wid  = tid >> 5;
    const int wm   = wid >> 2;       // 0..1
    const int wn   = wid & 3;        // 0..3
    const int warp_m = wm * 112;
    const int warp_n = wn * 32;
    const int cta_m0 = blockIdx.x * CTA_M;

    if (tid < CTA_M) scnt[tid] = 0;

    // ---- stage loader (A: 224x64 bf16, B: 128x64 bf16, SW swizzled) ----
    auto load_stage = [&](int gs) {
        const int t = gs >> 3, s = gs & 7;
        const int n0 = t << 7, k0 = s << 6;
        const uint32_t base = smS + (uint32_t)(gs & 3) * STAGE_B;
        #pragma unroll
        for (int i = 0; i < 7; i++) {           // A: 1792 16B chunks
            int idx = tid + (i << 8);
            int r = idx >> 3, c = idx & 7;
            int srow = cta_m0 + r;
            if (srow > M_Z - 1) srow = M_Z - 1;
            const void* src = g_zb + ((size_t)srow << 9) + k0 + (c << 3);
            uint32_t byte = ((uint32_t)r << 7) + ((uint32_t)c << 4);
            cp16(base + (byte ^ ((r & 7) << 4)), src);
        }
        #pragma unroll
        for (int i = 0; i < 4; i++) {           // B: 1024 16B chunks
            int idx = tid + (i << 8);
            int r = idx >> 3, c = idx & 7;
            const void* src = g_ub + ((size_t)(n0 + r) << 9) + k0 + (c << 3);
            uint32_t byte = ((uint32_t)r << 7) + ((uint32_t)c << 4);
            cp16(base + A_STAGE_B + (byte ^ ((r & 7) << 4)), src);
        }
    };

    // prologue: stages 0,1,2
    load_stage(0); CP_COMMIT();
    load_stage(1); CP_COMMIT();
    load_stage(2); CP_COMMIT();

    float acc[7][4][4];
    #pragma unroll
    for (int mi = 0; mi < 7; mi++)
        #pragma unroll
        for (int nj = 0; nj < 4; nj++)
            #pragma unroll
            for (int e = 0; e < 4; e++) acc[mi][nj][e] = 0.0f;

    float best0[7], best1[7];
    #pragma unroll
    for (int mi = 0; mi < 7; mi++) { best0[mi] = -3.4e38f; best1[mi] = -3.4e38f; }

    for (int gs = 0; gs < NSTAGES_K; gs++) {
        CP_WAIT(2);          // stage gs resident (3 groups were pending)
        __syncthreads();     // visibility + all warps done with buffer (gs-1)&3

        if (gs + 3 < NSTAGES_K) load_stage(gs + 3);
        CP_COMMIT();         // empty group at tail keeps the pending count math

        const uint32_t sA = smS + (uint32_t)(gs & 3) * STAGE_B;
        const uint32_t sB = sA + A_STAGE_B;

        #pragma unroll
        for (int s16 = 0; s16 < 4; s16++) {
            const int klane = s16 * 32 + ((lane >> 4) << 4);
            uint32_t a[7][4];
            #pragma unroll
            for (int mi = 0; mi < 7; mi++) {
                int m_r = warp_m + mi * 16 + (lane & 15);
                uint32_t ad = sA + ((((uint32_t)m_r << 7) + klane) ^ ((m_r & 7) << 4));
                ldmatrix_x4(a[mi], ad);
            }
            uint32_t b[2][4];
            #pragma unroll
            for (int ng = 0; ng < 2; ng++) {
                int n_r = warp_n + ng * 16 + (lane & 15);
                uint32_t bd = sB + ((((uint32_t)n_r << 7) + klane) ^ ((n_r & 7) << 4));
                ldmatrix_x4(b[ng], bd);
            }
            #pragma unroll
            for (int mi = 0; mi < 7; mi++)
                #pragma unroll
                for (int ng = 0; ng < 2; ng++) {
                    mma_bf16(acc[mi][2 * ng],     a[mi], b[ng][0], b[ng][2]);
                    mma_bf16(acc[mi][2 * ng + 1], a[mi], b[ng][1], b[ng][3]);
                }
        }

        if ((gs & 7) == 7) {
            // ---- tile epilogue: + beta, local running argmax, margin emit ----
            const int n0 = (gs >> 3) << 7;
            float2 be[4];
            #pragma unroll
            for (int nj = 0; nj < 4; nj++)
                be[nj] = *(const float2*)(g_beta + n0 + warp_n + nj * 8 + ((lane & 3) << 1));

            #pragma unroll
            for (int mi = 0; mi < 7; mi++) {
                float t0 = -3.4e38f, t1 = -3.4e38f;
                #pragma unroll
                for (int nj = 0; nj < 4; nj++) {
                    acc[mi][nj][0] += be[nj].x; acc[mi][nj][1] += be[nj].y;
                    acc[mi][nj][2] += be[nj].x; acc[mi][nj][3] += be[nj].y;
                    t0 = fmaxf(t0, fmaxf(acc[mi][nj][0], acc[mi][nj][1]));
                    t1 = fmaxf(t1, fmaxf(acc[mi][nj][2], acc[mi][nj][3]));
                }
                t0 = fmaxf(t0, __shfl_xor_sync(0xFFFFFFFFu, t0, 1));
                t0 = fmaxf(t0, __shfl_xor_sync(0xFFFFFFFFu, t0, 2));
                t1 = fmaxf(t1, __shfl_xor_sync(0xFFFFFFFFu, t1, 1));
                t1 = fmaxf(t1, __shfl_xor_sync(0xFFFFFFFFu, t1, 2));
                best0[mi] = fmaxf(best0[mi], t0);
                best1[mi] = fmaxf(best1[mi], t1);
                const float th0 = best0[mi] - MARGIN;
                const float th1 = best1[mi] - MARGIN;

                const int lr0 = warp_m + mi * 16 + (lane >> 2);
                const int gr0 = cta_m0 + lr0;
                const int ncol = n0 + warp_n + ((lane & 3) << 1);
                if (gr0 < M_Z) {
                    #pragma unroll
                    for (int nj = 0; nj < 4; nj++) {
                        if (acc[mi][nj][0] > th0) {
                            int sl = atomicAdd(&scnt[lr0], 1);
                            if (sl < CAP) g_cand[((size_t)gr0 << 5) + sl] = (unsigned)(ncol + nj * 8);
                        }
                        if (acc[mi][nj][1] > th0) {
                            int sl = atomicAdd(&scnt[lr0], 1);
                            if (sl < CAP) g_cand[((size_t)gr0 << 5) + sl] = (unsigned)(ncol + nj * 8 + 1);
                        }
                    }
                }
                if (gr0 + 8 < M_Z) {
                    #pragma unroll
                    for (int nj = 0; nj < 4; nj++) {
                        if (acc[mi][nj][2] > th1) {
                            int sl = atomicAdd(&scnt[lr0 + 8], 1);
                            if (sl < CAP) g_cand[((size_t)(gr0 + 8) << 5) + sl] = (unsigned)(ncol + nj * 8);
                        }
                        if (acc[mi][nj][3] > th1) {
                            int sl = atomicAdd(&scnt[lr0 + 8], 1);
                            if (sl < CAP) g_cand[((size_t)(gr0 + 8) << 5) + sl] = (unsigned)(ncol + nj * 8 + 1);
                        }
                    }
                }
                #pragma unroll
                for (int nj = 0; nj < 4; nj++) {
                    acc[mi][nj][0] = 0.0f; acc[mi][nj][1] = 0.0f;
                    acc[mi][nj][2] = 0.0f; acc[mi][nj][3] = 0.0f;
                }
            }
        }
    }

    __syncthreads();
    if (tid < CTA_M && cta_m0 + tid < M_Z) g_ccnt[cta_m0 + tid] = scnt[tid];
}

// ============================================================
// K6: exact fp32 rescore: s = z . u_n + beta_n.  One warp per z-row.
// ============================================================
__global__ __launch_bounds__(256)
void rescore(const float* __restrict__ z)
{
    const int row  = blockIdx.x * 8 + (threadIdx.x >> 5);
    const int lane = threadIdx.x & 31;
    const float* zp = z + (size_t)row * DIM;
    float4 zr[4];
    #pragma unroll
    for (int it = 0; it < 4; it++)
        zr[it] = *(const float4*)(zp + lane * 16 + it * 4);

    int cnt = g_ccnt[row];
    float bv = -3.4e38f;
    int   bi = 0x7FFFFFFF;

    if (cnt <= CAP) {
        for (int c = 0; c < cnt; c++) {
            int idx = (int)g_cand[((size_t)row << 5) + c];
            const float* ur = g_u + (size_t)idx * DIM;
            float s = 0.0f;
            #pragma unroll
            for (int it = 0; it < 4; it++) {
                float4 uv = *(const float4*)(ur + lane * 16 + it * 4);
                s = fmaf(zr[it].x, uv.x, s);
                s = fmaf(zr[it].y, uv.y, s);
                s = fmaf(zr[it].z, uv.z, s);
                s = fmaf(zr[it].w, uv.w, s);
            }
            #pragma unroll
            for (int o = 16; o > 0; o >>= 1) s += __shfl_xor_sync(0xFFFFFFFFu, s, o);
            s += g_beta[idx];
            if (s > bv || (s == bv && idx < bi)) { bv = s; bi = idx; }
        }
    } else {
        for (int n = 0; n < N_CB; n++) {
            const float* ur = g_u + (size_t)n * DIM;
            float s = 0.0f;
            #pragma unroll
            for (int it = 0; it < 4; it++) {
                float4 uv = *(const float4*)(ur + lane * 16 + it * 4);
                s = fmaf(zr[it].x, uv.x, s);
                s = fmaf(zr[it].y, uv.y, s);
                s = fmaf(zr[it].z, uv.z, s);
                s = fmaf(zr[it].w, uv.w, s);
            }
            #pragma unroll
            for (int o = 16; o > 0; o >>= 1) s += __shfl_xor_sync(0xFFFFFFFFu, s, o);
            s += g_beta[n];
            if (s > bv) { bv = s; bi = n; }
        }
    }
    if (lane == 0) g_idx[row] = bi;
}

// ============================================================
// K7: quantized = z + (q - z), per-row (q-z)^2 partial, idx tail
// ============================================================
__global__ void gather_loss(const float* __restrict__ z, float* __restrict__ out,
                            long long out_size)
{
    int row = blockIdx.x;
    int t   = threadIdx.x;   // 128 threads
    int id  = g_idx[row];
    const float* q  = g_qcb + (size_t)id * DIM;
    const float* zr = z + (size_t)row * DIM;
    float* oq = out + (size_t)row * DIM;

    float s = 0.0f;
    #pragma unroll
    for (int c = t * 4; c < DIM; c += 512) {
        float4 qv = *(const float4*)(q + c);
        float4 zv = *(const float4*)(zr + c);
        float4 o;
        float d;
        d = qv.x - zv.x; o.x = zv.x + d; s = fmaf(d, d, s);
        d = qv.y - zv.y; o.y = zv.y + d; s = fmaf(d, d, s);
        d = qv.z - zv.z; o.z = zv.z + d; s = fmaf(d, d, s);
        d = qv.w - zv.w; o.w = zv.w + d; s = fmaf(d, d, s);
        *(float4*)(oq + c) = o;
    }

    __shared__ float red[128];
    red[t] = s;
    __syncthreads();
    #pragma unroll
    for (int off = 64; off > 0; off >>= 1) {
        if (t < off) red[t] += red[t + off];
        __syncthreads();
    }
    if (t == 0) {
        g_partial[row] = red[0];
        long long pos = (long long)QN + 1 + row;
        if (pos < out_size) out[pos] = (float)id;
    }
}

__global__ void finalize_loss(float* __restrict__ out, long long out_size)
{
    __shared__ float red[256];
    int t = threadIdx.x;
    float s = 0.0f;
    for (int i = t; i < M_Z; i += 256) s += g_partial[i];
    red[t] = s;
    __syncthreads();
    #pragma unroll
    for (int off = 128; off > 0; off >>= 1) {
        if (t < off) red[t] += red[t + off];
        __syncthreads();
    }
    if (t == 0 && (long long)QN < out_size)
        out[QN] = red[0] * (1.25f / 16777216.0f);
}

__global__ void zero_range(float* __restrict__ out, long long begin, long long end)
{
    long long stride = (long long)gridDim.x * blockDim.x;
    for (long long i = begin + (long long)blockIdx.x * blockDim.x + threadIdx.x;
         i < end; i += stride)
        out[i] = 0.0f;
}

// ============================================================
extern "C" void kernel_launch(void* const* d_in, const int* in_sizes, int n_in,
                              void* d_out, int out_size)
{
    const float* z     = (const float*)d_in[0];   // [8,4096,512]
    const float* emb   = (const float*)d_in[1];   // [8192,512]
    const float* emb_w = (const float*)d_in[2];   // [512,512]
    const float* emb_b = (const float*)d_in[3];   // [512]
    const float* zw    = (const float*)d_in[4];   // [512,512]
    const float* zb    = (const float*)d_in[5];   // [512]
    // d_in[6] = l2_scale: positive per-row scaling, argmin-invariant -> unused
    float* out = (float*)d_out;
    long long osz = (long long)out_size;

    cudaFuncSetAttribute(coarse_kernel,
                         cudaFuncAttributeMaxDynamicSharedMemorySize, COARSE_SMEM);

    // K1: quant_codebook = emb @ emb_w^T + emb_b
    gemm_bias_nt<<<dim3(4, 64), 256>>>(emb, emb_w, emb_b, DIM);
    // K2: row norms + beta
    rownorm_beta<<<N_CB / 8, 256>>>(zb);
    // K3: U = diag(1/||c||)(qcb @ zw)
    gemm_nn_scaled<<<dim3(4, 64), 256>>>(zw);
    // K4: z -> bf16
    convert_z<<<2048, 256>>>(z);
    // K5: bf16 HMMA coarse pass, single wave -> candidates
    coarse_kernel<<<GRID_COARSE, 256, COARSE_SMEM>>>();
    // K6: exact fp32 rescore -> g_idx
    rescore<<<M_Z / 8, 256>>>(z);
    // K7: outputs
    gather_loss<<<M_Z, 128>>>(z, out, osz);
    finalize_loss<<<1, 256>>>(out, osz);
    long long need = (long long)QN + 1 + M_Z;
    if (osz > need) zero_range<<<256, 256>>>(out, need, osz);
}

// round 8
// speedup vs baseline: 1.3276x; 1.3276x over previous
#include <cuda_runtime.h>
#include <cuda_bf16.h>
#include <cstdint>

#define DIM   512
#define N_CB  8192
#define M_Z   32768
#define QN    16777216   // M_Z * DIM
#define CAP   32
#define MARGIN 0.5f

// coarse geometry: 256 CTAs x 128 rows, warp tile m16 x n128
#define SMA_BYTES   65536            // A band: 128 rows x 512B int8
#define SMB_STAGE   8192             // B stage: 128 codes x 64B
#define SMB_OFF     SMA_BYTES
#define SCNT_OFF    (SMA_BYTES + 4 * SMB_STAGE)   // 98304
#define COARSE_SMEM (SCNT_OFF + 512)              // 98816
#define NSTAGES_K   512              // 64 n-tiles * 8 k64-slices

// ---- scratch (device globals; no allocation) ----
__device__ float   g_qcb[(size_t)N_CB * DIM];   // quant_codebook fp32
__device__ float   g_u  [(size_t)N_CB * DIM];   // U fp32 (rescore)
__device__ int8_t  g_uq [(size_t)N_CB * DIM];   // U int8
__device__ int8_t  g_zq [(size_t)M_Z * DIM];    // z int8
__device__ float   g_zs [M_Z];                  // per-row z scale
__device__ float2  g_sb [N_CB];                 // (su, beta) per code
__device__ float   g_rs  [N_CB];
__device__ float   g_beta[N_CB];
__device__ unsigned g_cand[(size_t)M_Z * CAP];
__device__ int     g_ccnt[M_Z];
__device__ int     g_idx[M_Z];
__device__ float   g_partial[M_Z];

// ============================================================
// base-ISA PTX helpers
// ============================================================
__device__ __forceinline__ uint32_t smem_u32(const void* p) {
    uint32_t a;
    asm("{ .reg .u64 t; cvta.to.shared.u64 t, %1; cvt.u32.u64 %0, t; }" : "=r"(a) : "l"(p));
    return a;
}
__device__ __forceinline__ void cp16(uint32_t dst, const void* src) {
    asm volatile("cp.async.cg.shared.global [%0], [%1], 16;" :: "r"(dst), "l"(src) : "memory");
}
#define CP_COMMIT() asm volatile("cp.async.commit_group;" ::: "memory")
#define CP_WAIT(N)  asm volatile("cp.async.wait_group %0;" :: "n"(N) : "memory")

__device__ __forceinline__ void ldmatrix_x4(uint32_t* r, uint32_t addr) {
    asm volatile("ldmatrix.sync.aligned.m8n8.x4.shared.b16 {%0,%1,%2,%3}, [%4];"
        : "=r"(r[0]), "=r"(r[1]), "=r"(r[2]), "=r"(r[3]) : "r"(addr));
}
__device__ __forceinline__ void imma_s8(int* d, const uint32_t* a, uint32_t b0, uint32_t b1) {
    asm volatile("mma.sync.aligned.m16n8k32.row.col.s32.s8.s8.s32 "
        "{%0,%1,%2,%3}, {%4,%5,%6,%7}, {%8,%9}, {%0,%1,%2,%3};"
        : "+r"(d[0]), "+r"(d[1]), "+r"(d[2]), "+r"(d[3])
        : "r"(a[0]), "r"(a[1]), "r"(a[2]), "r"(a[3]), "r"(b0), "r"(b1));
}

// ============================================================
// K1: qcb = emb @ emb_w^T + emb_b   (NT, fp32)
// ============================================================
__global__ __launch_bounds__(256, 2)
void gemm_bias_nt(const float* __restrict__ A, const float* __restrict__ W,
                  const float* __restrict__ bias, int K)
{
    __shared__ float As[16][128];
    __shared__ float Ws[16][128];
    const int tid = threadIdx.x;
    const int tx  = tid & 15;
    const int ty  = tid >> 4;
    const int row0 = blockIdx.y * 128;
    const int col0 = blockIdx.x * 128;

    float acc[8][8];
    #pragma unroll
    for (int i = 0; i < 8; i++)
        #pragma unroll
        for (int j = 0; j < 8; j++) acc[i][j] = 0.0f;

    for (int k0 = 0; k0 < K; k0 += 16) {
        #pragma unroll
        for (int v = tid; v < 512; v += 256) {
            int r  = v >> 2;
            int kc = (v & 3) << 2;
            float4 a = *(const float4*)(A + (size_t)(row0 + r) * K + k0 + kc);
            As[kc + 0][r] = a.x; As[kc + 1][r] = a.y;
            As[kc + 2][r] = a.z; As[kc + 3][r] = a.w;
            float4 w = *(const float4*)(W + (size_t)(col0 + r) * K + k0 + kc);
            Ws[kc + 0][r] = w.x; Ws[kc + 1][r] = w.y;
            Ws[kc + 2][r] = w.z; Ws[kc + 3][r] = w.w;
        }
        __syncthreads();
        #pragma unroll
        for (int kk = 0; kk < 16; kk++) {
            float a[8], b[8];
            *(float4*)(a)     = *(const float4*)&As[kk][ty * 8];
            *(float4*)(a + 4) = *(const float4*)&As[kk][ty * 8 + 4];
            *(float4*)(b)     = *(const float4*)&Ws[kk][tx * 8];
            *(float4*)(b + 4) = *(const float4*)&Ws[kk][tx * 8 + 4];
            #pragma unroll
            for (int i = 0; i < 8; i++)
                #pragma unroll
                for (int j = 0; j < 8; j++)
                    acc[i][j] = fmaf(a[i], b[j], acc[i][j]);
        }
        __syncthreads();
    }

    float bs[8];
    #pragma unroll
    for (int j = 0; j < 8; j++) bs[j] = bias[col0 + tx * 8 + j];

    #pragma unroll
    for (int i = 0; i < 8; i++) {
        size_t row = (size_t)(row0 + ty * 8 + i);
        float* cp = g_qcb + row * DIM + col0 + tx * 8;
        *(float4*)(cp)     = make_float4(acc[i][0]+bs[0], acc[i][1]+bs[1], acc[i][2]+bs[2], acc[i][3]+bs[3]);
        *(float4*)(cp + 4) = make_float4(acc[i][4]+bs[4], acc[i][5]+bs[5], acc[i][6]+bs[6], acc[i][7]+bs[7]);
    }
}

// ============================================================
// K2: per-row 1/||c|| and beta = (z_proj_b . c)/||c||
// ============================================================
__global__ void rownorm_beta(const float* __restrict__ zpb)
{
    int row  = blockIdx.x * 8 + (threadIdx.x >> 5);
    int lane = threadIdx.x & 31;
    const float* x = g_qcb + (size_t)row * DIM;
    float s2 = 0.0f, sb = 0.0f;
    #pragma unroll
    for (int it = 0; it < 4; it++) {
        float4 v = *(const float4*)(x + lane * 4 + it * 128);
        float4 b = *(const float4*)(zpb + lane * 4 + it * 128);
        s2 += v.x*v.x + v.y*v.y + v.z*v.z + v.w*v.w;
        sb += v.x*b.x + v.y*b.y + v.z*b.z + v.w*b.w;
    }
    #pragma unroll
    for (int off = 16; off > 0; off >>= 1) {
        s2 += __shfl_xor_sync(0xFFFFFFFFu, s2, off);
        sb += __shfl_xor_sync(0xFFFFFFFFu, sb, off);
    }
    float rs = 1.0f / fmaxf(sqrtf(s2), 1e-12f);
    if (lane == 0) { g_rs[row] = rs; g_beta[row] = sb * rs; }
}

// ============================================================
// K3: U = (g_qcb @ W) * rs[row]   (NN, fp32) -> g_u
// ============================================================
__global__ __launch_bounds__(256, 2)
void gemm_nn_scaled(const float* __restrict__ W)
{
    __shared__ float As[16][128];
    __shared__ float Ws[16][128];
    const int tid = threadIdx.x;
    const int tx  = tid & 15;
    const int ty  = tid >> 4;
    const int row0 = blockIdx.y * 128;
    const int col0 = blockIdx.x * 128;
    const float* __restrict__ A = g_qcb;

    float acc[8][8];
    #pragma unroll
    for (int i = 0; i < 8; i++)
        #pragma unroll
        for (int j = 0; j < 8; j++) acc[i][j] = 0.0f;

    for (int k0 = 0; k0 < DIM; k0 += 16) {
        #pragma unroll
        for (int v = tid; v < 512; v += 256) {
            int r  = v >> 2;
            int kc = (v & 3) << 2;
            float4 a = *(const float4*)(A + (size_t)(row0 + r) * DIM + k0 + kc);
            As[kc + 0][r] = a.x; As[kc + 1][r] = a.y;
            As[kc + 2][r] = a.z; As[kc + 3][r] = a.w;
        }
        #pragma unroll
        for (int v = tid; v < 512; v += 256) {
            int kk = v >> 5;
            int nc = (v & 31) * 4;
            float4 w = *(const float4*)(W + (size_t)(k0 + kk) * DIM + col0 + nc);
            *(float4*)&Ws[kk][nc] = w;
        }
        __syncthreads();
        #pragma unroll
        for (int kk = 0; kk < 16; kk++) {
            float a[8], b[8];
            *(float4*)(a)     = *(const float4*)&As[kk][ty * 8];
            *(float4*)(a + 4) = *(const float4*)&As[kk][ty * 8 + 4];
            *(float4*)(b)     = *(const float4*)&Ws[kk][tx * 8];
            *(float4*)(b + 4) = *(const float4*)&Ws[kk][tx * 8 + 4];
            #pragma unroll
            for (int i = 0; i < 8; i++)
                #pragma unroll
                for (int j = 0; j < 8; j++)
                    acc[i][j] = fmaf(a[i], b[j], acc[i][j]);
        }
        __syncthreads();
    }

    #pragma unroll
    for (int i = 0; i < 8; i++) {
        size_t row = (size_t)(row0 + ty * 8 + i);
        float s = g_rs[row];
        float* up = g_u + row * DIM + col0 + tx * 8;
        *(float4*)(up)     = make_float4(acc[i][0]*s, acc[i][1]*s, acc[i][2]*s, acc[i][3]*s);
        *(float4*)(up + 4) = make_float4(acc[i][4]*s, acc[i][5]*s, acc[i][6]*s, acc[i][7]*s);
    }
}

// ============================================================
// quantize rows of a fp32 matrix to int8 with per-row maxabs scale.
// warp per row. mode 0: z -> g_zq/g_zs.  mode 1: g_u -> g_uq/g_sb.
// ============================================================
__global__ void quantize_rows(const float* __restrict__ src, int mode)
{
    int row  = blockIdx.x * 8 + (threadIdx.x >> 5);
    int lane = threadIdx.x & 31;
    const float* x = (mode == 0) ? (src + (size_t)row * DIM) : (g_u + (size_t)row * DIM);

    float4 v[4];
    float mx = 0.0f;
    #pragma unroll
    for (int it = 0; it < 4; it++) {
        v[it] = *(const float4*)(x + lane * 4 + it * 128);
        mx = fmaxf(mx, fmaxf(fmaxf(fabsf(v[it].x), fabsf(v[it].y)),
                             fmaxf(fabsf(v[it].z), fabsf(v[it].w))));
    }
    #pragma unroll
    for (int off = 16; off > 0; off >>= 1)
        mx = fmaxf(mx, __shfl_xor_sync(0xFFFFFFFFu, mx, off));
    float sc  = fmaxf(mx, 1e-12f) / 127.0f;
    float inv = 1.0f / sc;

    int8_t* dst = (mode == 0) ? (g_zq + (size_t)row * DIM) : (g_uq + (size_t)row * DIM);
    #pragma unroll
    for (int it = 0; it < 4; it++) {
        int q0 = max(-127, min(127, __float2int_rn(v[it].x * inv)));
        int q1 = max(-127, min(127, __float2int_rn(v[it].y * inv)));
        int q2 = max(-127, min(127, __float2int_rn(v[it].z * inv)));
        int q3 = max(-127, min(127, __float2int_rn(v[it].w * inv)));
        uint32_t packed = (uint32_t)(q0 & 0xFF) | ((uint32_t)(q1 & 0xFF) << 8)
                        | ((uint32_t)(q2 & 0xFF) << 16) | ((uint32_t)(q3 & 0xFF) << 24);
        *(uint32_t*)(dst + lane * 4 + it * 128) = packed;
    }
    if (lane == 0) {
        if (mode == 0) g_zs[row] = sc;
        else           g_sb[row] = make_float2(sc, g_beta[row]);
    }
}

// ============================================================
// K5: coarse int8 IMMA pass + margin candidate collection.
// 256 CTAs x 128 rows; A band (64KB int8) resident; B in 4-stage
// cp.async ring (8KB/stage). 8 warps, warp tile m16 x n128.
// ============================================================
__global__ __launch_bounds__(256, 2)
void coarse_kernel()
{
    extern __shared__ char sm[];
    const uint32_t smA = smem_u32(sm);
    int* scnt = (int*)(sm + SCNT_OFF);

    const int tid  = threadIdx.x;
    const int lane = tid & 31;
    const int wid  = tid >> 5;
    const int row0 = blockIdx.x * 128;
    const int warp_m = wid << 4;

    if (tid < 128) scnt[tid] = 0;

    // ---- A band: 128 rows x 512B int8, chunk-swizzled (c ^= r&7) ----
    #pragma unroll
    for (int i = 0; i < 16; i++) {
        int idx = tid + (i << 8);
        int r = idx >> 5, c = idx & 31;
        const void* src = g_zq + ((size_t)(row0 + r) << 9) + (c << 4);
        cp16(smA + ((uint32_t)r << 9) + (uint32_t)((c ^ (r & 7)) << 4), src);
    }
    // ---- B stage loader: 128 codes x 64B, swizzle c ^= (r>>1)&3 ----
    auto load_stage = [&](int gs) {
        const int n0 = (gs >> 3) << 7, k0 = (gs & 7) << 6;
        const uint32_t base = smA + SMB_OFF + (uint32_t)(gs & 3) * SMB_STAGE;
        #pragma unroll
        for (int i = 0; i < 2; i++) {
            int idx = tid + (i << 8);
            int r = idx >> 2, c = idx & 3;
            const void* src = g_uq + ((size_t)(n0 + r) << 9) + k0 + (c << 4);
            cp16(base + ((uint32_t)r << 6) + (uint32_t)((c ^ ((r >> 1) & 3)) << 4), src);
        }
    };

    load_stage(0); CP_COMMIT();       // group 0: A band + stage 0
    load_stage(1); CP_COMMIT();
    load_stage(2); CP_COMMIT();

    int acc[16][4];
    #pragma unroll
    for (int i = 0; i < 16; i++)
        #pragma unroll
        for (int j = 0; j < 4; j++) acc[i][j] = 0;

    const int lr0 = warp_m + (lane >> 2);
    const float sz0 = g_zs[row0 + lr0];
    const float sz1 = g_zs[row0 + lr0 + 8];
    float best0 = -3.4e38f, best1 = -3.4e38f;

    const int tl   = lane >> 3;       // ldmatrix tile index 0..3
    const int trow = lane & 7;

    for (int gs = 0; gs < NSTAGES_K; gs++) {
        CP_WAIT(2);
        __syncthreads();
        if (gs + 3 < NSTAGES_K) load_stage(gs + 3);
        CP_COMMIT();

        const uint32_t sB = smA + SMB_OFF + (uint32_t)(gs & 3) * SMB_STAGE;
        const int s = gs & 7;

        #pragma unroll
        for (int h = 0; h < 2; h++) {
            // A fragment: rows warp_m..+15, k-bytes [64s+32h, +32)
            uint32_t a[4];
            {
                int r = warp_m + trow + ((tl & 1) << 3);
                int c = (s << 2) + (h << 1) + (tl >> 1);
                ldmatrix_x4(a, smA + ((uint32_t)r << 9) + (uint32_t)((c ^ (r & 7)) << 4));
            }
            #pragma unroll
            for (int p = 0; p < 8; p++) {
                uint32_t b[4];
                int r = (p << 4) + trow + ((tl & 1) << 3);
                int c = (h << 1) + (tl >> 1);
                ldmatrix_x4(b, sB + ((uint32_t)r << 6) + (uint32_t)((c ^ ((r >> 1) & 3)) << 4));
                imma_s8(acc[2 * p],     a, b[0], b[2]);
                imma_s8(acc[2 * p + 1], a, b[1], b[3]);
            }
        }

        if ((gs & 7) == 7) {
            const int n0 = (gs >> 3) << 7;
            float t0 = -3.4e38f, t1 = -3.4e38f;
            #pragma unroll
            for (int ni = 0; ni < 16; ni++) {
                int nb = n0 + (ni << 3) + ((lane & 3) << 1);
                float4 sb = *(const float4*)(g_sb + nb);   // (su0,b0,su1,b1)
                float s0 = fmaf(sz0 * sb.x, (float)acc[ni][0], sb.y);
                float s1 = fmaf(sz0 * sb.z, (float)acc[ni][1], sb.w);
                float s2 = fmaf(sz1 * sb.x, (float)acc[ni][2], sb.y);
                float s3 = fmaf(sz1 * sb.z, (float)acc[ni][3], sb.w);
                acc[ni][0] = __float_as_int(s0);
                acc[ni][1] = __float_as_int(s1);
                acc[ni][2] = __float_as_int(s2);
                acc[ni][3] = __float_as_int(s3);
                t0 = fmaxf(t0, fmaxf(s0, s1));
                t1 = fmaxf(t1, fmaxf(s2, s3));
            }
            t0 = fmaxf(t0, __shfl_xor_sync(0xFFFFFFFFu, t0, 1));
            t0 = fmaxf(t0, __shfl_xor_sync(0xFFFFFFFFu, t0, 2));
            t1 = fmaxf(t1, __shfl_xor_sync(0xFFFFFFFFu, t1, 1));
            t1 = fmaxf(t1, __shfl_xor_sync(0xFFFFFFFFu, t1, 2));
            best0 = fmaxf(best0, t0);
            best1 = fmaxf(best1, t1);
            const float th0 = best0 - MARGIN, th1 = best1 - MARGIN;
            const int gr0 = row0 + lr0;

            #pragma unroll
            for (int ni = 0; ni < 16; ni++) {
                int nb = n0 + (ni << 3) + ((lane & 3) << 1);
                if (__int_as_float(acc[ni][0]) > th0) {
                    int sl = atomicAdd(&scnt[lr0], 1);
                    if (sl < CAP) g_cand[((size_t)gr0 << 5) + sl] = (unsigned)nb;
                }
                if (__int_as_float(acc[ni][1]) > th0) {
                    int sl = atomicAdd(&scnt[lr0], 1);
                    if (sl < CAP) g_cand[((size_t)gr0 << 5) + sl] = (unsigned)(nb + 1);
                }
                if (__int_as_float(acc[ni][2]) > th1) {
                    int sl = atomicAdd(&scnt[lr0 + 8], 1);
                    if (sl < CAP) g_cand[((size_t)(gr0 + 8) << 5) + sl] = (unsigned)nb;
                }
                if (__int_as_float(acc[ni][3]) > th1) {
                    int sl = atomicAdd(&scnt[lr0 + 8], 1);
                    if (sl < CAP) g_cand[((size_t)(gr0 + 8) << 5) + sl] = (unsigned)(nb + 1);
                }
                acc[ni][0] = 0; acc[ni][1] = 0; acc[ni][2] = 0; acc[ni][3] = 0;
            }
        }
    }

    __syncthreads();
    if (tid < 128) g_ccnt[row0 + tid] = scnt[tid];
}

// ============================================================
// K6: exact fp32 rescore: s = z . u_n + beta_n.  One warp per z-row.
// ============================================================
__global__ __launch_bounds__(256)
void rescore(const float* __restrict__ z)
{
    const int row  = blockIdx.x * 8 + (threadIdx.x >> 5);
    const int lane = threadIdx.x & 31;
    const float* zp = z + (size_t)row * DIM;
    float4 zr[4];
    #pragma unroll
    for (int it = 0; it < 4; it++)
        zr[it] = *(const float4*)(zp + lane * 16 + it * 4);

    int cnt = g_ccnt[row];
    float bv = -3.4e38f;
    int   bi = 0x7FFFFFFF;

    if (cnt <= CAP) {
        for (int c = 0; c < cnt; c++) {
            int idx = (int)g_cand[((size_t)row << 5) + c];
            const float* ur = g_u + (size_t)idx * DIM;
            float s = 0.0f;
            #pragma unroll
            for (int it = 0; it < 4; it++) {
                float4 uv = *(const float4*)(ur + lane * 16 + it * 4);
                s = fmaf(zr[it].x, uv.x, s);
                s = fmaf(zr[it].y, uv.y, s);
                s = fmaf(zr[it].z, uv.z, s);
                s = fmaf(zr[it].w, uv.w, s);
            }
            #pragma unroll
            for (int o = 16; o > 0; o >>= 1) s += __shfl_xor_sync(0xFFFFFFFFu, s, o);
            s += g_beta[idx];
            if (s > bv || (s == bv && idx < bi)) { bv = s; bi = idx; }
        }
    } else {
        for (int n = 0; n < N_CB; n++) {
            const float* ur = g_u + (size_t)n * DIM;
            float s = 0.0f;
            #pragma unroll
            for (int it = 0; it < 4; it++) {
                float4 uv = *(const float4*)(ur + lane * 16 + it * 4);
                s = fmaf(zr[it].x, uv.x, s);
                s = fmaf(zr[it].y, uv.y, s);
                s = fmaf(zr[it].z, uv.z, s);
                s = fmaf(zr[it].w, uv.w, s);
            }
            #pragma unroll
            for (int o = 16; o > 0; o >>= 1) s += __shfl_xor_sync(0xFFFFFFFFu, s, o);
            s += g_beta[n];
            if (s > bv) { bv = s; bi = n; }
        }
    }
    if (lane == 0) g_idx[row] = bi;
}

// ============================================================
// K7: quantized = z + (q - z), per-row (q-z)^2 partial, idx tail
// ============================================================
__global__ void gather_loss(const float* __restrict__ z, float* __restrict__ out,
                            long long out_size)
{
    int row = blockIdx.x;
    int t   = threadIdx.x;   // 128 threads
    int id  = g_idx[row];
    const float* q  = g_qcb + (size_t)id * DIM;
    const float* zr = z + (size_t)row * DIM;
    float* oq = out + (size_t)row * DIM;

    float s = 0.0f;
    #pragma unroll
    for (int c = t * 4; c < DIM; c += 512) {
        float4 qv = *(const float4*)(q + c);
        float4 zv = *(const float4*)(zr + c);
        float4 o;
        float d;
        d = qv.x - zv.x; o.x = zv.x + d; s = fmaf(d, d, s);
        d = qv.y - zv.y; o.y = zv.y + d; s = fmaf(d, d, s);
        d = qv.z - zv.z; o.z = zv.z + d; s = fmaf(d, d, s);
        d = qv.w - zv.w; o.w = zv.w + d; s = fmaf(d, d, s);
        *(float4*)(oq + c) = o;
    }

    __shared__ float red[128];
    red[t] = s;
    __syncthreads();
    #pragma unroll
    for (int off = 64; off > 0; off >>= 1) {
        if (t < off) red[t] += red[t + off];
        __syncthreads();
    }
    if (t == 0) {
        g_partial[row] = red[0];
        long long pos = (long long)QN + 1 + row;
        if (pos < out_size) out[pos] = (float)id;
    }
}

__global__ void finalize_loss(float* __restrict__ out, long long out_size)
{
    __shared__ float red[256];
    int t = threadIdx.x;
    float s = 0.0f;
    for (int i = t; i < M_Z; i += 256) s += g_partial[i];
    red[t] = s;
    __syncthreads();
    #pragma unroll
    for (int off = 128; off > 0; off >>= 1) {
        if (t < off) red[t] += red[t + off];
        __syncthreads();
    }
    if (t == 0 && (long long)QN < out_size)
        out[QN] = red[0] * (1.25f / 16777216.0f);
}

__global__ void zero_range(float* __restrict__ out, long long begin, long long end)
{
    long long stride = (long long)gridDim.x * blockDim.x;
    for (long long i = begin + (long long)blockIdx.x * blockDim.x + threadIdx.x;
         i < end; i += stride)
        out[i] = 0.0f;
}

// ============================================================
extern "C" void kernel_launch(void* const* d_in, const int* in_sizes, int n_in,
                              void* d_out, int out_size)
{
    const float* z     = (const float*)d_in[0];   // [8,4096,512]
    const float* emb   = (const float*)d_in[1];   // [8192,512]
    const float* emb_w = (const float*)d_in[2];   // [512,512]
    const float* emb_b = (const float*)d_in[3];   // [512]
    const float* zw    = (const float*)d_in[4];   // [512,512]
    const float* zb    = (const float*)d_in[5];   // [512]
    // d_in[6] = l2_scale: positive per-row scaling, argmin-invariant -> unused
    float* out = (float*)d_out;
    long long osz = (long long)out_size;

    cudaFuncSetAttribute(coarse_kernel,
                         cudaFuncAttributeMaxDynamicSharedMemorySize, COARSE_SMEM);

    // K1: quant_codebook = emb @ emb_w^T + emb_b
    gemm_bias_nt<<<dim3(4, 64), 256>>>(emb, emb_w, emb_b, DIM);
    // K2: row norms + beta
    rownorm_beta<<<N_CB / 8, 256>>>(zb);
    // K3: U = diag(1/||c||)(qcb @ zw)
    gemm_nn_scaled<<<dim3(4, 64), 256>>>(zw);
    // quantize z and U to int8 (per-row maxabs scales)
    quantize_rows<<<M_Z / 8, 256>>>(z, 0);
    quantize_rows<<<N_CB / 8, 256>>>(nullptr, 1);
    // K5: int8 IMMA coarse pass -> candidates
    coarse_kernel<<<M_Z / 128, 256, COARSE_SMEM>>>();
    // K6: exact fp32 rescore -> g_idx
    rescore<<<M_Z / 8, 256>>>(z);
    // K7: outputs
    gather_loss<<<M_Z, 128>>>(z, out, osz);
    finalize_loss<<<1, 256>>>(out, osz);
    long long need = (long long)QN + 1 + M_Z;
    if (osz > need) zero_range<<<256, 256>>>(out, need, osz);
}

// round 12
// speedup vs baseline: 7.5737x; 5.7049x over previous
#include <cuda_runtime.h>
#include <cuda_bf16.h>
#include <cstdint>

#define DIM   512
#define N_CB  8192
#define M_Z   32768
#define QN    16777216   // M_Z * DIM
#define CAP   32
#define MARGIN 0.2f

// coarse geometry: 512 CTAs x 64 rows, 2 CTAs/SM (112KB smem)
#define CTA_M       64
#define SMA_BYTES   65536                 // A band: 64 rows x 1KB bf16
#define SMB_STAGE   16384                 // B stage: 128 codes x 128B (k64)
#define NSTG        3
#define SCNT_OFF    (SMA_BYTES + NSTG * SMB_STAGE)   // 114688
#define COARSE_SMEM (SCNT_OFF + 256)                 // 114944
#define NSTAGES_K   512                   // 64 n-tiles * 8 k64-slices

// ---- scratch (device globals; no allocation) ----
__device__ float g_qcb[(size_t)N_CB * DIM];           // quant_codebook fp32
__device__ float g_u  [(size_t)N_CB * DIM];           // U fp32 (rescore)
__device__ __nv_bfloat16 g_ub[(size_t)N_CB * DIM];    // U bf16
__device__ __nv_bfloat16 g_zb[(size_t)M_Z * DIM];     // z bf16
__device__ float g_rs  [N_CB];                        // 1/||c||
__device__ float g_beta[N_CB];                        // (b . c)/||c||
__device__ unsigned g_cand[(size_t)M_Z * CAP];
__device__ int   g_ccnt[M_Z];
__device__ int   g_idx[M_Z];
__device__ float g_partial[M_Z];

// ============================================================
// base-ISA PTX helpers
// ============================================================
__device__ __forceinline__ uint32_t smem_u32(const void* p) {
    uint32_t a;
    asm("{ .reg .u64 t; cvta.to.shared.u64 t, %1; cvt.u32.u64 %0, t; }" : "=r"(a) : "l"(p));
    return a;
}
__device__ __forceinline__ void cp16(uint32_t dst, const void* src) {
    asm volatile("cp.async.cg.shared.global [%0], [%1], 16;" :: "r"(dst), "l"(src) : "memory");
}
#define CP_COMMIT() asm volatile("cp.async.commit_group;" ::: "memory")
#define CP_WAIT(N)  asm volatile("cp.async.wait_group %0;" :: "n"(N) : "memory")

__device__ __forceinline__ void ldmatrix_x4(uint32_t* r, uint32_t addr) {
    asm volatile("ldmatrix.sync.aligned.m8n8.x4.shared.b16 {%0,%1,%2,%3}, [%4];"
        : "=r"(r[0]), "=r"(r[1]), "=r"(r[2]), "=r"(r[3]) : "r"(addr));
}
__device__ __forceinline__ void mma_bf16(float* d, const uint32_t* a, uint32_t b0, uint32_t b1) {
    asm volatile("mma.sync.aligned.m16n8k16.row.col.f32.bf16.bf16.f32 "
        "{%0,%1,%2,%3}, {%4,%5,%6,%7}, {%8,%9}, {%0,%1,%2,%3};"
        : "+f"(d[0]), "+f"(d[1]), "+f"(d[2]), "+f"(d[3])
        : "r"(a[0]), "r"(a[1]), "r"(a[2]), "r"(a[3]), "r"(b0), "r"(b1));
}

// ============================================================
// K1: qcb = emb @ emb_w^T + emb_b   (NT, fp32)
// ============================================================
__global__ __launch_bounds__(256, 2)
void gemm_bias_nt(const float* __restrict__ A, const float* __restrict__ W,
                  const float* __restrict__ bias, int K)
{
    __shared__ float As[16][128];
    __shared__ float Ws[16][128];
    const int tid = threadIdx.x;
    const int tx  = tid & 15;
    const int ty  = tid >> 4;
    const int row0 = blockIdx.y * 128;
    const int col0 = blockIdx.x * 128;

    float acc[8][8];
    #pragma unroll
    for (int i = 0; i < 8; i++)
        #pragma unroll
        for (int j = 0; j < 8; j++) acc[i][j] = 0.0f;

    for (int k0 = 0; k0 < K; k0 += 16) {
        #pragma unroll
        for (int v = tid; v < 512; v += 256) {
            int r  = v >> 2;
            int kc = (v & 3) << 2;
            float4 a = *(const float4*)(A + (size_t)(row0 + r) * K + k0 + kc);
            As[kc + 0][r] = a.x; As[kc + 1][r] = a.y;
            As[kc + 2][r] = a.z; As[kc + 3][r] = a.w;
            float4 w = *(const float4*)(W + (size_t)(col0 + r) * K + k0 + kc);
            Ws[kc + 0][r] = w.x; Ws[kc + 1][r] = w.y;
            Ws[kc + 2][r] = w.z; Ws[kc + 3][r] = w.w;
        }
        __syncthreads();
        #pragma unroll
        for (int kk = 0; kk < 16; kk++) {
            float a[8], b[8];
            *(float4*)(a)     = *(const float4*)&As[kk][ty * 8];
            *(float4*)(a + 4) = *(const float4*)&As[kk][ty * 8 + 4];
            *(float4*)(b)     = *(const float4*)&Ws[kk][tx * 8];
            *(float4*)(b + 4) = *(const float4*)&Ws[kk][tx * 8 + 4];
            #pragma unroll
            for (int i = 0; i < 8; i++)
                #pragma unroll
                for (int j = 0; j < 8; j++)
                    acc[i][j] = fmaf(a[i], b[j], acc[i][j]);
        }
        __syncthreads();
    }

    float bs[8];
    #pragma unroll
    for (int j = 0; j < 8; j++) bs[j] = bias[col0 + tx * 8 + j];

    #pragma unroll
    for (int i = 0; i < 8; i++) {
        size_t row = (size_t)(row0 + ty * 8 + i);
        float* cp = g_qcb + row * DIM + col0 + tx * 8;
        *(float4*)(cp)     = make_float4(acc[i][0]+bs[0], acc[i][1]+bs[1], acc[i][2]+bs[2], acc[i][3]+bs[3]);
        *(float4*)(cp + 4) = make_float4(acc[i][4]+bs[4], acc[i][5]+bs[5], acc[i][6]+bs[6], acc[i][7]+bs[7]);
    }
}

// ============================================================
// K2: per-row 1/||c|| and beta = (z_proj_b . c)/||c||
// ============================================================
__global__ void rownorm_beta(const float* __restrict__ zpb)
{
    int row  = blockIdx.x * 8 + (threadIdx.x >> 5);
    int lane = threadIdx.x & 31;
    const float* x = g_qcb + (size_t)row * DIM;
    float s2 = 0.0f, sb = 0.0f;
    #pragma unroll
    for (int it = 0; it < 4; it++) {
        float4 v = *(const float4*)(x + lane * 4 + it * 128);
        float4 b = *(const float4*)(zpb + lane * 4 + it * 128);
        s2 += v.x*v.x + v.y*v.y + v.z*v.z + v.w*v.w;
        sb += v.x*b.x + v.y*b.y + v.z*b.z + v.w*b.w;
    }
    #pragma unroll
    for (int off = 16; off > 0; off >>= 1) {
        s2 += __shfl_xor_sync(0xFFFFFFFFu, s2, off);
        sb += __shfl_xor_sync(0xFFFFFFFFu, sb, off);
    }
    float rs = 1.0f / fmaxf(sqrtf(s2), 1e-12f);
    if (lane == 0) { g_rs[row] = rs; g_beta[row] = sb * rs; }
}

// ============================================================
// K3: U = (g_qcb @ W) * rs[row]   (NN, fp32) -> g_u fp32 + g_ub bf16
// ============================================================
__global__ __launch_bounds__(256, 2)
void gemm_nn_scaled(const float* __restrict__ W)
{
    __shared__ float As[16][128];
    __shared__ float Ws[16][128];
    const int tid = threadIdx.x;
    const int tx  = tid & 15;
    const int ty  = tid >> 4;
    const int row0 = blockIdx.y * 128;
    const int col0 = blockIdx.x * 128;
    const float* __restrict__ A = g_qcb;

    float acc[8][8];
    #pragma unroll
    for (int i = 0; i < 8; i++)
        #pragma unroll
        for (int j = 0; j < 8; j++) acc[i][j] = 0.0f;

    for (int k0 = 0; k0 < DIM; k0 += 16) {
        #pragma unroll
        for (int v = tid; v < 512; v += 256) {
            int r  = v >> 2;
            int kc = (v & 3) << 2;
            float4 a = *(const float4*)(A + (size_t)(row0 + r) * DIM + k0 + kc);
            As[kc + 0][r] = a.x; As[kc + 1][r] = a.y;
            As[kc + 2][r] = a.z; As[kc + 3][r] = a.w;
        }
        #pragma unroll
        for (int v = tid; v < 512; v += 256) {
            int kk = v >> 5;
            int nc = (v & 31) * 4;
            float4 w = *(const float4*)(W + (size_t)(k0 + kk) * DIM + col0 + nc);
            *(float4*)&Ws[kk][nc] = w;
        }
        __syncthreads();
        #pragma unroll
        for (int kk = 0; kk < 16; kk++) {
            float a[8], b[8];
            *(float4*)(a)     = *(const float4*)&As[kk][ty * 8];
            *(float4*)(a + 4) = *(const float4*)&As[kk][ty * 8 + 4];
            *(float4*)(b)     = *(const float4*)&Ws[kk][tx * 8];
            *(float4*)(b + 4) = *(const float4*)&Ws[kk][tx * 8 + 4];
            #pragma unroll
            for (int i = 0; i < 8; i++)
                #pragma unroll
                for (int j = 0; j < 8; j++)
                    acc[i][j] = fmaf(a[i], b[j], acc[i][j]);
        }
        __syncthreads();
    }

    #pragma unroll
    for (int i = 0; i < 8; i++) {
        size_t row = (size_t)(row0 + ty * 8 + i);
        float s = g_rs[row];
        float o[8];
        #pragma unroll
        for (int j = 0; j < 8; j++) o[j] = acc[i][j] * s;
        float* up = g_u + row * DIM + col0 + tx * 8;
        *(float4*)(up)     = make_float4(o[0], o[1], o[2], o[3]);
        *(float4*)(up + 4) = make_float4(o[4], o[5], o[6], o[7]);
        __nv_bfloat162* bp = (__nv_bfloat162*)(g_ub + row * DIM + col0 + tx * 8);
        bp[0] = __floats2bfloat162_rn(o[0], o[1]);
        bp[1] = __floats2bfloat162_rn(o[2], o[3]);
        bp[2] = __floats2bfloat162_rn(o[4], o[5]);
        bp[3] = __floats2bfloat162_rn(o[6], o[7]);
    }
}

// ============================================================
// K4: z -> bf16
// ============================================================
__global__ void convert_z(const float* __restrict__ z)
{
    long long n4 = QN / 4;
    long long stride = (long long)gridDim.x * blockDim.x;
    for (long long i = (long long)blockIdx.x * blockDim.x + threadIdx.x; i < n4; i += stride) {
        float4 v = ((const float4*)z)[i];
        __nv_bfloat162 p0 = __floats2bfloat162_rn(v.x, v.y);
        __nv_bfloat162 p1 = __floats2bfloat162_rn(v.z, v.w);
        uint2 o;
        o.x = *(uint32_t*)&p0;
        o.y = *(uint32_t*)&p1;
        ((uint2*)g_zb)[i] = o;
    }
}

// ============================================================
// K5: coarse bf16 HMMA pass (r6 structure, 2-CTA/SM geometry).
// 512 CTAs x 64 rows. A band (64KB) resident; B 3-stage ring.
// 8 warps as 4(m) x 2(n): warp tile m16 x n64.
// ============================================================
__global__ __launch_bounds__(256, 2)
void coarse_kernel()
{
    extern __shared__ char sm[];
    const uint32_t smA = smem_u32(sm);
    int* scnt = (int*)(sm + SCNT_OFF);

    const int tid  = threadIdx.x;
    const int lane = tid & 31;
    const int wid  = tid >> 5;
    const int warp_m = (wid >> 1) << 4;    // 0,16,32,48
    const int warp_n = (wid & 1) << 6;     // 0,64
    const int row0 = blockIdx.x * CTA_M;
    const int l8   = lane & 7;
    const int quad = lane >> 3;

    if (tid < CTA_M) scnt[tid] = 0;

    // ---- A band: 64 rows x 512 bf16 (1KB/row), swizzled ----
    #pragma unroll
    for (int i = 0; i < 16; i++) {
        int idx = tid + (i << 8);
        int r = idx >> 6, c = idx & 63;
        const void* src = g_zb + ((size_t)(row0 + r) << 9) + (c << 3);
        uint32_t byte = ((uint32_t)r << 10) + ((uint32_t)c << 4);
        cp16(smA + (byte ^ ((r & 7) << 4)), src);
    }
    // ---- B stage loader: 128 codes x 64 bf16 (128B/row), swizzled ----
    auto load_stage = [&](int gs, int slot) {
        const int n0 = (gs >> 3) << 7, k0 = (gs & 7) << 6;
        const uint32_t base = smA + SMA_BYTES + (uint32_t)slot * SMB_STAGE;
        #pragma unroll
        for (int i = 0; i < 4; i++) {
            int idx = tid + (i << 8);
            int r = idx >> 3, c = idx & 7;
            const void* src = g_ub + ((size_t)(n0 + r) << 9) + k0 + (c << 3);
            uint32_t byte = ((uint32_t)r << 7) + ((uint32_t)c << 4);
            cp16(base + (byte ^ ((r & 7) << 4)), src);
        }
    };

    load_stage(0, 0); CP_COMMIT();   // group: A band + stage 0
    load_stage(1, 1); CP_COMMIT();

    float acc[8][4];
    #pragma unroll
    for (int i = 0; i < 8; i++)
        #pragma unroll
        for (int j = 0; j < 4; j++) acc[i][j] = 0.0f;

    float best0 = -3.4e38f, best1 = -3.4e38f;
    const int lr0 = warp_m + (lane >> 2);

    int slot_c = 0, slot_l = 2;

    for (int gs = 0; gs < NSTAGES_K; gs++) {
        CP_WAIT(1);
        __syncthreads();

        if (gs + 2 < NSTAGES_K) load_stage(gs + 2, slot_l);
        CP_COMMIT();
        slot_l = (slot_l == 2) ? 0 : slot_l + 1;

        const uint32_t sB = smA + SMA_BYTES + (uint32_t)slot_c * SMB_STAGE;
        slot_c = (slot_c == 2) ? 0 : slot_c + 1;
        const int s = gs & 7;

        #pragma unroll
        for (int s16 = 0; s16 < 4; s16++) {
            uint32_t a[4];
            {
                int m_r = warp_m + l8 + ((quad & 1) << 3);
                int bc  = s * 128 + s16 * 32 + ((quad >> 1) << 4);
                ldmatrix_x4(a, smA + ((((uint32_t)m_r << 10) + bc) ^ ((m_r & 7) << 4)));
            }
            #pragma unroll
            for (int ng = 0; ng < 4; ng++) {
                uint32_t b[4];
                int n_r = warp_n + (ng << 4) + l8 + ((quad & 1) << 3);
                int bc  = s16 * 32 + ((quad >> 1) << 4);
                ldmatrix_x4(b, sB + ((((uint32_t)n_r << 7) + bc) ^ ((n_r & 7) << 4)));
                mma_bf16(acc[2 * ng],     a, b[0], b[2]);
                mma_bf16(acc[2 * ng + 1], a, b[1], b[3]);
            }
        }

        if ((gs & 7) == 7) {
            // ---- tile epilogue: + beta, running argmax, margin emit ----
            const int n0 = (gs >> 3) << 7;
            float t0 = -3.4e38f, t1 = -3.4e38f;
            #pragma unroll
            for (int ai = 0; ai < 8; ai++) {
                int nb = n0 + warp_n + ((ai >> 1) << 4) + ((ai & 1) << 3) + ((lane & 3) << 1);
                float2 be = *(const float2*)(g_beta + nb);
                acc[ai][0] += be.x; acc[ai][1] += be.y;
                acc[ai][2] += be.x; acc[ai][3] += be.y;
                t0 = fmaxf(t0, fmaxf(acc[ai][0], acc[ai][1]));
                t1 = fmaxf(t1, fmaxf(acc[ai][2], acc[ai][3]));
            }
            t0 = fmaxf(t0, __shfl_xor_sync(0xFFFFFFFFu, t0, 1));
            t0 = fmaxf(t0, __shfl_xor_sync(0xFFFFFFFFu, t0, 2));
            t1 = fmaxf(t1, __shfl_xor_sync(0xFFFFFFFFu, t1, 1));
            t1 = fmaxf(t1, __shfl_xor_sync(0xFFFFFFFFu, t1, 2));
            best0 = fmaxf(best0, t0);
            best1 = fmaxf(best1, t1);
            const float th0 = best0 - MARGIN, th1 = best1 - MARGIN;
            const int gr0 = row0 + lr0;

            #pragma unroll
            for (int ai = 0; ai < 8; ai++) {
                int nb = n0 + warp_n + ((ai >> 1) << 4) + ((ai & 1) << 3) + ((lane & 3) << 1);
                if (acc[ai][0] > th0) {
                    int sl = atomicAdd(&scnt[lr0], 1);
                    if (sl < CAP) g_cand[((size_t)gr0 << 5) + sl] = (unsigned)nb;
                }
                if (acc[ai][1] > th0) {
                    int sl = atomicAdd(&scnt[lr0], 1);
                    if (sl < CAP) g_cand[((size_t)gr0 << 5) + sl] = (unsigned)(nb + 1);
                }
                if (acc[ai][2] > th1) {
                    int sl = atomicAdd(&scnt[lr0 + 8], 1);
                    if (sl < CAP) g_cand[((size_t)(gr0 + 8) << 5) + sl] = (unsigned)nb;
                }
                if (acc[ai][3] > th1) {
                    int sl = atomicAdd(&scnt[lr0 + 8], 1);
                    if (sl < CAP) g_cand[((size_t)(gr0 + 8) << 5) + sl] = (unsigned)(nb + 1);
                }
                acc[ai][0] = 0.0f; acc[ai][1] = 0.0f;
                acc[ai][2] = 0.0f; acc[ai][3] = 0.0f;
            }
        }
    }

    __syncthreads();
    if (tid < CTA_M) g_ccnt[row0 + tid] = scnt[tid];
}

// ============================================================
// K6: exact fp32 rescore: s = z . u_n + beta_n.  One warp per z-row.
// ============================================================
__global__ __launch_bounds__(256)
void rescore(const float* __restrict__ z)
{
    const int row  = blockIdx.x * 8 + (threadIdx.x >> 5);
    const int lane = threadIdx.x & 31;
    const float* zp = z + (size_t)row * DIM;
    float4 zr[4];
    #pragma unroll
    for (int it = 0; it < 4; it++)
        zr[it] = *(const float4*)(zp + lane * 16 + it * 4);

    int cnt = g_ccnt[row];
    float bv = -3.4e38f;
    int   bi = 0x7FFFFFFF;

    if (cnt <= CAP) {
        for (int c = 0; c < cnt; c++) {
            int idx = (int)g_cand[((size_t)row << 5) + c];
            const float* ur = g_u + (size_t)idx * DIM;
            float s = 0.0f;
            #pragma unroll
            for (int it = 0; it < 4; it++) {
                float4 uv = *(const float4*)(ur + lane * 16 + it * 4);
                s = fmaf(zr[it].x, uv.x, s);
                s = fmaf(zr[it].y, uv.y, s);
                s = fmaf(zr[it].z, uv.z, s);
                s = fmaf(zr[it].w, uv.w, s);
            }
            #pragma unroll
            for (int o = 16; o > 0; o >>= 1) s += __shfl_xor_sync(0xFFFFFFFFu, s, o);
            s += g_beta[idx];
            if (s > bv || (s == bv && idx < bi)) { bv = s; bi = idx; }
        }
    } else {
        for (int n = 0; n < N_CB; n++) {
            const float* ur = g_u + (size_t)n * DIM;
            float s = 0.0f;
            #pragma unroll
            for (int it = 0; it < 4; it++) {
                float4 uv = *(const float4*)(ur + lane * 16 + it * 4);
                s = fmaf(zr[it].x, uv.x, s);
                s = fmaf(zr[it].y, uv.y, s);
                s = fmaf(zr[it].z, uv.z, s);
                s = fmaf(zr[it].w, uv.w, s);
            }
            #pragma unroll
            for (int o = 16; o > 0; o >>= 1) s += __shfl_xor_sync(0xFFFFFFFFu, s, o);
            s += g_beta[n];
            if (s > bv) { bv = s; bi = n; }
        }
    }
    if (lane == 0) g_idx[row] = bi;
}

// ============================================================
// K7: quantized = z + (q - z), per-row (q-z)^2 partial, idx tail
// ============================================================
__global__ void gather_loss(const float* __restrict__ z, float* __restrict__ out,
                            long long out_size)
{
    int row = blockIdx.x;
    int t   = threadIdx.x;   // 128 threads
    int id  = g_idx[row];
    const float* q  = g_qcb + (size_t)id * DIM;
    const float* zr = z + (size_t)row * DIM;
    float* oq = out + (size_t)row * DIM;

    float s = 0.0f;
    #pragma unroll
    for (int c = t * 4; c < DIM; c += 512) {
        float4 qv = *(const float4*)(q + c);
        float4 zv = *(const float4*)(zr + c);
        float4 o;
        float d;
        d = qv.x - zv.x; o.x = zv.x + d; s = fmaf(d, d, s);
        d = qv.y - zv.y; o.y = zv.y + d; s = fmaf(d, d, s);
        d = qv.z - zv.z; o.z = zv.z + d; s = fmaf(d, d, s);
        d = qv.w - zv.w; o.w = zv.w + d; s = fmaf(d, d, s);
        *(float4*)(oq + c) = o;
    }

    __shared__ float red[128];
    red[t] = s;
    __syncthreads();
    #pragma unroll
    for (int off = 64; off > 0; off >>= 1) {
        if (t < off) red[t] += red[t + off];
        __syncthreads();
    }
    if (t == 0) {
        g_partial[row] = red[0];
        long long pos = (long long)QN + 1 + row;
        if (pos < out_size) out[pos] = (float)id;
    }
}

__global__ void finalize_loss(float* __restrict__ out, long long out_size)
{
    __shared__ float red[256];
    int t = threadIdx.x;
    float s = 0.0f;
    for (int i = t; i < M_Z; i += 256) s += g_partial[i];
    red[t] = s;
    __syncthreads();
    #pragma unroll
    for (int off = 128; off > 0; off >>= 1) {
        if (t < off) red[t] += red[t + off];
        __syncthreads();
    }
    if (t == 0 && (long long)QN < out_size)
        out[QN] = red[0] * (1.25f / 16777216.0f);
}

__global__ void zero_range(float* __restrict__ out, long long begin, long long end)
{
    long long stride = (long long)gridDim.x * blockDim.x;
    for (long long i = begin + (long long)blockIdx.x * blockDim.x + threadIdx.x;
         i < end; i += stride)
        out[i] = 0.0f;
}

// ============================================================
extern "C" void kernel_launch(void* const* d_in, const int* in_sizes, int n_in,
                              void* d_out, int out_size)
{
    const float* z     = (const float*)d_in[0];   // [8,4096,512]
    const float* emb   = (const float*)d_in[1];   // [8192,512]
    const float* emb_w = (const float*)d_in[2];   // [512,512]
    const float* emb_b = (const float*)d_in[3];   // [512]
    const float* zw    = (const float*)d_in[4];   // [512,512]
    const float* zb    = (const float*)d_in[5];   // [512]
    // d_in[6] = l2_scale: positive per-row scaling, argmin-invariant -> unused
    float* out = (float*)d_out;
    long long osz = (long long)out_size;

    cudaFuncSetAttribute(coarse_kernel,
                         cudaFuncAttributeMaxDynamicSharedMemorySize, COARSE_SMEM);

    // K1: quant_codebook = emb @ emb_w^T + emb_b
    gemm_bias_nt<<<dim3(4, 64), 256>>>(emb, emb_w, emb_b, DIM);
    // K2: row norms + beta
    rownorm_beta<<<N_CB / 8, 256>>>(zb);
    // K3: U = diag(1/||c||)(qcb @ zw)
    gemm_nn_scaled<<<dim3(4, 64), 256>>>(zw);
    // K4: z -> bf16
    convert_z<<<2048, 256>>>(z);
    // K5: bf16 HMMA coarse pass (2 CTAs/SM) -> candidates
    coarse_kernel<<<M_Z / CTA_M, 256, COARSE_SMEM>>>();
    // K6: exact fp32 rescore -> g_idx
    rescore<<<M_Z / 8, 256>>>(z);
    // K7: outputs
    gather_loss<<<M_Z, 128>>>(z, out, osz);
    finalize_loss<<<1, 256>>>(out, osz);
    long long need = (long long)QN + 1 + M_Z;
    if (osz > need) zero_range<<<256, 256>>>(out, need, osz);
}